// round 13
// baseline (speedup 1.0000x reference)
#include <cuda_runtime.h>
#include <math.h>

#define B_ 4
#define N_ 8192

constexpr int   NBUCKET = 1024;
constexpr float RLO   = -6.0f;
constexpr float BWID  = 12.0f / NBUCKET;
constexpr float INVBW = NBUCKET / 12.0f;

constexpr int BTPB      = 1024;                // build/SL launch block size
constexpr int BUILD_BLOCKS = 2 * B_;           // 8
constexpr int SL_BLOCKS = 56;                  // blocks 8..63 of build launch
constexpr int QTPB      = 128;                 // query block size (4 independent warps)
constexpr int WSEG      = 32;                  // queries per warp = chunk size
constexpr int QWARPS    = 2 * B_ * (N_ / WSEG);  // 2048
constexpr int QBLOCKS   = QWARPS / (QTPB / 32);  // 512
constexpr int FTPB      = 1024;

// Scratch (write-once per call; no init needed).
__device__ float4 g_sorted[2][B_][N_];             // bucket-ordered, .w = ||p||^2
__device__ int    g_bstart[2][B_][NBUCKET + 1];    // bucket start offsets
__device__ float  g_part[3 * SL_BLOCKS];           // small-loss partials
__device__ float  g_qpart[QWARPS];                 // per-warp sum of sqrt(min d2)

// ---------------- K1: blocks 0-7 bucket build, blocks 8-63 small losses ----------------
__global__ void build_sl_kernel(const float* __restrict__ pred,
                                const float* __restrict__ targ) {
    __shared__ int sA[NBUCKET];
    __shared__ int sB[NBUCKET];
    const int tid = threadIdx.x;

    if (blockIdx.x < BUILD_BLOCKS) {
        // ======== counting sort by x0 (exact since R7), with w=||p||^2 ========
        const int cloud = blockIdx.x >> 2;
        const int b     = blockIdx.x & 3;
        const float* src = (cloud ? targ : pred) + b * N_ * 3;

        sA[tid] = 0;
        __syncthreads();

        float4 pt[8];
        int    bk[8];
#pragma unroll
        for (int i = 0; i < 8; i++) {
            int k = tid + i * NBUCKET;
            float x0 = src[k * 3], x1 = src[k * 3 + 1], x2 = src[k * 3 + 2];
            pt[i] = make_float4(x0, x1, x2, fmaf(x0, x0, fmaf(x1, x1, x2 * x2)));
            int q = (int)floorf((x0 - RLO) * INVBW);
            q = min(max(q, 0), NBUCKET - 1);
            bk[i] = q;
            atomicAdd(&sA[q], 1);
        }
        __syncthreads();

        int* pin = sA;
        int* pout = sB;
        for (int o = 1; o < NBUCKET; o <<= 1) {
            pout[tid] = pin[tid] + ((tid >= o) ? pin[tid - o] : 0);
            __syncthreads();
            int* t = pin; pin = pout; pout = t;
        }
        const int excl = tid ? pin[tid - 1] : 0;
        g_bstart[cloud][b][tid] = excl;
        if (tid == NBUCKET - 1) g_bstart[cloud][b][NBUCKET] = pin[NBUCKET - 1];

        pout[tid] = excl;
        __syncthreads();
#pragma unroll
        for (int i = 0; i < 8; i++) {
            int pos = atomicAdd(&pout[bk[i]], 1);
            g_sorted[cloud][b][pos] = pt[i];
        }
        return;
    }

    // ======== small losses ========
    float* red = (float*)sA;
    const int blk = blockIdx.x - BUILD_BLOCKS;
    const int gid = blk * BTPB + tid;
    const int gsz = SL_BLOCKS * BTPB;   // 57344

    const float4* p4 = (const float4*)pred;
    const float4* t4 = (const float4*)targ;
    float s = 0.f;
    for (int i = gid; i < B_ * N_ * 3 / 4; i += gsz) {
        float4 a = p4[i], bb = t4[i];
        float d0 = a.x - bb.x, d1 = a.y - bb.y, d2 = a.z - bb.z, d3 = a.w - bb.w;
        s = fmaf(d0, d0, fmaf(d1, d1, fmaf(d2, d2, fmaf(d3, d3, s))));
    }
    red[tid] = s; __syncthreads();
    for (int o = BTPB / 2; o > 0; o >>= 1) {
        if (tid < o) red[tid] += red[tid + o];
        __syncthreads();
    }
    if (tid == 0) g_part[0 * SL_BLOCKS + blk] = red[0];
    __syncthreads();

    s = 0.f;
    for (int b = 0; b < B_; b++) {
        const float* pb = pred + b * N_ * 3;
        for (int k = gid; k < N_ - 1; k += gsz) {
            const float* p = pb + k * 3;
            float dx = p[3] - p[0], dy = p[4] - p[1], dz = p[5] - p[2];
            s += sqrtf(fmaf(dx, dx, fmaf(dy, dy, dz * dz)));
        }
    }
    red[tid] = s; __syncthreads();
    for (int o = BTPB / 2; o > 0; o >>= 1) {
        if (tid < o) red[tid] += red[tid + o];
        __syncthreads();
    }
    if (tid == 0) g_part[1 * SL_BLOCKS + blk] = red[0];
    __syncthreads();

    s = 0.f;
    const int mid = N_ / 2;
    for (int b = 0; b < B_; b++) {
        const float* pb = pred + b * N_ * 3;
        for (int k = gid; k < mid; k += gsz) {
            const float* l = pb + k * 3;
            const float* r = pb + (N_ - 1 - k) * 3;
            float d0 = l[0] + r[0];
            float d1 = l[1] - r[1];
            float d2 = l[2] - r[2];
            s += fmaf(d0, d0, fmaf(d1, d1, d2 * d2));
        }
    }
    red[tid] = s; __syncthreads();
    for (int o = BTPB / 2; o > 0; o >>= 1) {
        if (tid < o) red[tid] += red[tid + o];
        __syncthreads();
    }
    if (tid == 0) g_part[2 * SL_BLOCKS + blk] = red[0];
}

// Fixed-32 chunk scan; partial d2' = ||p||^2 - 2 q.p  (add ||q||^2 at the end).
// 5 inst/candidate: LDS.128 (broadcast) + 3 FMA + FMNMX; 4 accumulators.
__device__ __forceinline__ float scan32(const float4* __restrict__ buf,
                                        float m2x, float m2y, float m2z,
                                        float best) {
    float b0 = best, b1 = 3.0e38f, b2 = 3.0e38f, b3 = 3.0e38f;
#pragma unroll
    for (int k = 0; k < WSEG; k += 4) {
        float4 p0 = buf[k], p1 = buf[k + 1], p2 = buf[k + 2], p3 = buf[k + 3];
        b0 = fminf(b0, fmaf(p0.x, m2x, fmaf(p0.y, m2y, fmaf(p0.z, m2z, p0.w))));
        b1 = fminf(b1, fmaf(p1.x, m2x, fmaf(p1.y, m2y, fmaf(p1.z, m2z, p1.w))));
        b2 = fminf(b2, fmaf(p2.x, m2x, fmaf(p2.y, m2y, fmaf(p2.z, m2z, p2.w))));
        b3 = fminf(b3, fmaf(p3.x, m2x, fmaf(p3.y, m2y, fmaf(p3.z, m2z, p3.w))));
    }
    return fminf(fminf(b0, b1), fminf(b2, b3));
}

// ---------------- K2: per-warp autonomous NN query (no block barriers) ----------------
__global__ void __launch_bounds__(QTPB)
query_kernel() {
    __shared__ __align__(16) float4 sbuf[QTPB / 32][2][WSEG];   // 4KB

    const int lane = threadIdx.x & 31;
    const int wid  = threadIdx.x >> 5;
    const int gw   = blockIdx.x * (QTPB / 32) + wid;   // 0..2047
    const int seg  = gw & 255;                         // 256 segments of 32 queries
    const int b    = (gw >> 8) & 3;
    const int dir  = gw >> 10;
    const float4* src    = g_sorted[dir][b];
    const float4* dst    = g_sorted[dir ^ 1][b];
    const int*    starts = g_bstart[dir ^ 1][b];

    const float4 q  = src[seg * WSEG + lane];
    const float m2x = -2.f * q.x, m2y = -2.f * q.y, m2z = -2.f * q.z;
    const float q2  = q.w;                    // ||q||^2 (from build)
    float best = 3.0e38f;                     // partial: ||p||^2 - 2 q.p
    bool doneL = false, doneR = false;

    // warp-uniform starting cursor from middle query's bucket
    const float midx = __shfl_sync(0xffffffffu, q.x, 16);
    int c = (int)floorf((midx - RLO) * INVBW);
    c = min(max(c, 0), NBUCKET - 1);
    int hi = starts[c];                       // next R index (uniform)
    int lo = hi;                              // L boundary (uniform)

    const float4 sentinel = make_float4(0.f, 0.f, 0.f, 3.0e38f);
    float4* bR = &sbuf[wid][0][0];
    float4* bL = &sbuf[wid][1][0];

    for (int iter = 0; iter < 2 * (N_ / WSEG) + 4; iter++) {
        const bool allR = __all_sync(0xffffffffu, doneR);
        const bool allL = __all_sync(0xffffffffu, doneL);
        if (allR && allL) break;

        const int cntR = (!allR && hi < N_) ? min(WSEG, N_ - hi) : 0;
        const int cntL = (!allL && lo > 0)  ? min(WSEG, lo)      : 0;

        if (cntR > 0) bR[lane] = (lane < cntR) ? dst[hi + lane] : sentinel;
        if (cntL > 0) bL[lane] = (lane < cntL) ? dst[lo - cntL + lane] : sentinel;
        __syncwarp();

        if (cntR > 0) {
            best = scan32(bR, m2x, m2y, m2z, best);
            float fr = bR[cntR - 1].x - BWID;     // future R: x >= fr
            float dr = fr - q.x;
            if (dr > 0.f && dr * dr > best + q2) doneR = true;
            hi += cntR;
        }
        if (hi >= N_) doneR = true;

        if (cntL > 0) {
            best = scan32(bL, m2x, m2y, m2z, best);
            float fl = bL[0].x + BWID;            // future L: x <= fl
            float dl = q.x - fl;
            if (dl > 0.f && dl * dl > best + q2) doneL = true;
            lo -= cntL;
        }
        if (lo <= 0) doneL = true;
        __syncwarp();   // buffers consumed before next overwrite
    }

    // warp sum of sqrt(min d2)
    float v = sqrtf(fmaxf(best + q2, 0.f));
#pragma unroll
    for (int o = 16; o > 0; o >>= 1)
        v += __shfl_xor_sync(0xffffffffu, v, o);
    if (lane == 0) g_qpart[gw] = v;
}

// ---------------- K3: final scalar ----------------
__global__ void final_kernel(float* __restrict__ out) {
    __shared__ float red[FTPB];
    __shared__ float sums[4];
    const int tid = threadIdx.x;

    float s = 0.f;
    for (int i = tid; i < QWARPS; i += FTPB) s += g_qpart[i];
    red[tid] = s; __syncthreads();
    for (int o = FTPB / 2; o > 0; o >>= 1) {
        if (tid < o) red[tid] += red[tid + o];
        __syncthreads();
    }
    if (tid == 0) sums[3] = red[0];
    __syncthreads();

#pragma unroll
    for (int t = 0; t < 3; t++) {
        s = (tid < SL_BLOCKS) ? g_part[t * SL_BLOCKS + tid] : 0.f;
        red[tid] = s; __syncthreads();
        for (int o = FTPB / 2; o > 0; o >>= 1) {
            if (tid < o) red[tid] += red[tid + o];
            __syncthreads();
        }
        if (tid == 0) sums[t] = red[0];
        __syncthreads();
    }

    if (tid == 0) {
        float vertex_loss  = sums[0] / (float)(B_ * N_ * 3);
        float smooth_loss  = sums[1] / (float)(B_ * (N_ - 1));
        float sym_loss     = sums[2] / (float)(B_ * (N_ / 2) * 3);
        float chamfer_loss = sums[3] / (float)(B_ * N_);
        out[0] = 1.0f * vertex_loss + 0.1f * smooth_loss
               + 0.05f * sym_loss + 0.1f * chamfer_loss;
    }
}

extern "C" void kernel_launch(void* const* d_in, const int* in_sizes, int n_in,
                              void* d_out, int out_size) {
    const float* pred = (const float*)d_in[0];
    const float* targ = (const float*)d_in[1];
    float* out = (float*)d_out;
    (void)in_sizes; (void)n_in; (void)out_size;

    build_sl_kernel<<<BUILD_BLOCKS + SL_BLOCKS, BTPB>>>(pred, targ);
    query_kernel<<<QBLOCKS, QTPB>>>();
    final_kernel<<<1, FTPB>>>(out);
}

// round 14
// speedup vs baseline: 1.7846x; 1.7846x over previous
#include <cuda_runtime.h>
#include <math.h>

#define B_ 4
#define N_ 8192

constexpr int TPB   = 128;              // threads per block
constexpr int PPT   = 8;                // x per thread (4 packed pairs)
constexpr int XPB   = TPB * PPT;        // 1024 x per block
constexpr int XT    = N_ / XPB;         // 8 x tiles
constexpr int SEG   = 256;              // y per block
constexpr int YS    = N_ / SEG;         // 32 y segments
constexpr int NWARP = TPB / 32;         // 4
constexpr int CHAM_BLOCKS = XT * YS * B_;   // 1024
constexpr int SL_BLOCKS   = 160;            // 1024+160 = 1184 = 8*148
constexpr int RED_BLOCKS  = 64;
constexpr int FTPB  = 256;

// Partial-min scratch: every slot written exactly once per call (no init/atomics).
__device__ float g_rowpart[YS * B_ * N_];   // pred-side mins per y-segment (4MB)
__device__ float g_colpart[XT * B_ * N_];   // targ-side mins per x-tile   (1MB)
__device__ float g_part[3 * SL_BLOCKS];     // small-loss block partials
__device__ float g_part2[RED_BLOCKS];       // chamfer sqrt-sum partials
__device__ int   g_done;                    // zero-initialized; reset by last block

union F2 { unsigned long long u; float2 f; };

__device__ __forceinline__ unsigned long long fma2(unsigned long long a,
                                                   unsigned long long b,
                                                   unsigned long long c) {
    unsigned long long d;
    asm("fma.rn.f32x2 %0, %1, %2, %3;" : "=l"(d) : "l"(a), "l"(b), "l"(c));
    return d;
}
__device__ __forceinline__ unsigned long long add2(unsigned long long a,
                                                   unsigned long long b) {
    unsigned long long d;
    asm("add.rn.f32x2 %0, %1, %2;" : "=l"(d) : "l"(a), "l"(b));
    return d;
}
__device__ __forceinline__ unsigned long long dup2(float v) {
    F2 r; r.f = make_float2(v, v); return r.u;
}

// ------------- megakernel: 160 small-loss blocks + 1024 chamfer blocks -------------
__global__ void __launch_bounds__(TPB, 8)
mega_kernel(const float* __restrict__ pred, const float* __restrict__ targ) {
    // 32B per y row: [0]=-2y0 dup, [1]=-2y1 dup, [2]=-2y2 dup, [3]=yw dup
    __shared__ __align__(16) unsigned long long sy[SEG][4];   // 8KB
    __shared__ float scol[NWARP][SEG];                        // 4KB
    __shared__ float red[TPB];                                // .5KB

    const int tid = threadIdx.x;

    if (blockIdx.x < SL_BLOCKS) {
        // ======== small losses ========
        const int gid = blockIdx.x * TPB + tid;
        const int gsz = SL_BLOCKS * TPB;          // 20480

        const float4* p4 = (const float4*)pred;
        const float4* t4 = (const float4*)targ;
        float s = 0.f;
        for (int i = gid; i < B_ * N_ * 3 / 4; i += gsz) {
            float4 a = p4[i], b = t4[i];
            float d0 = a.x - b.x, d1 = a.y - b.y, d2 = a.z - b.z, d3 = a.w - b.w;
            s = fmaf(d0, d0, fmaf(d1, d1, fmaf(d2, d2, fmaf(d3, d3, s))));
        }
        red[tid] = s; __syncthreads();
        for (int o = TPB / 2; o > 0; o >>= 1) {
            if (tid < o) red[tid] += red[tid + o];
            __syncthreads();
        }
        if (tid == 0) g_part[0 * SL_BLOCKS + blockIdx.x] = red[0];
        __syncthreads();

        // smoothness
        s = 0.f;
        for (int b = 0; b < B_; b++) {
            const float* pb = pred + b * N_ * 3;
            for (int k = gid; k < N_ - 1; k += gsz) {
                const float* p = pb + k * 3;
                float dx = p[3] - p[0], dy = p[4] - p[1], dz = p[5] - p[2];
                s += sqrtf(fmaf(dx, dx, fmaf(dy, dy, dz * dz)));
            }
        }
        red[tid] = s; __syncthreads();
        for (int o = TPB / 2; o > 0; o >>= 1) {
            if (tid < o) red[tid] += red[tid + o];
            __syncthreads();
        }
        if (tid == 0) g_part[1 * SL_BLOCKS + blockIdx.x] = red[0];
        __syncthreads();

        // symmetry
        s = 0.f;
        const int mid = N_ / 2;
        for (int b = 0; b < B_; b++) {
            const float* pb = pred + b * N_ * 3;
            for (int k = gid; k < mid; k += gsz) {
                const float* l = pb + k * 3;
                const float* r = pb + (N_ - 1 - k) * 3;
                float d0 = l[0] + r[0];
                float d1 = l[1] - r[1];
                float d2 = l[2] - r[2];
                s += fmaf(d0, d0, fmaf(d1, d1, d2 * d2));
            }
        }
        red[tid] = s; __syncthreads();
        for (int o = TPB / 2; o > 0; o >>= 1) {
            if (tid < o) red[tid] += red[tid + o];
            __syncthreads();
        }
        if (tid == 0) g_part[2 * SL_BLOCKS + blockIdx.x] = red[0];
        return;
    }

    // ======== symmetric-fused chamfer ========
    const int cc = blockIdx.x - SL_BLOCKS;
    const int xt = cc & (XT - 1);            // 8
    const int ys = (cc >> 3) & (YS - 1);     // 32
    const int b  = cc >> 8;                  // 4
    const int lane = tid & 31;
    const int wid  = tid >> 5;

    // load + fold targ segment (256 y)
    const float* Yb = targ + b * N_ * 3;
    const int m0 = ys * SEG;
    for (int j = tid; j < SEG; j += TPB) {
        const float* y = Yb + (m0 + j) * 3;
        float y0 = y[0], y1 = y[1], y2 = y[2];
        float yw = fmaf(y0, y0, fmaf(y1, y1, y2 * y2));
        sy[j][0] = dup2(-2.f * y0);
        sy[j][1] = dup2(-2.f * y1);
        sy[j][2] = dup2(-2.f * y2);
        sy[j][3] = dup2(yw);
    }
    __syncthreads();

    // load 8 pred points/thread as 4 packed pairs (p, p+4)
    const float* Xb = pred + b * N_ * 3;
    const int pbase = xt * XPB + tid;

    F2 xp0[4], xp1[4], xp2[4], xnp[4];
    float rmA[4], rmB[4];
#pragma unroll
    for (int p = 0; p < 4; p++) {
        const float* xa = Xb + (pbase + p * TPB) * 3;
        const float* xb = Xb + (pbase + (p + 4) * TPB) * 3;
        float a0 = xa[0], a1 = xa[1], a2 = xa[2];
        float b0 = xb[0], b1 = xb[1], b2 = xb[2];
        xp0[p].f = make_float2(a0, b0);
        xp1[p].f = make_float2(a1, b1);
        xp2[p].f = make_float2(a2, b2);
        xnp[p].f = make_float2(fmaf(a0, a0, fmaf(a1, a1, a2 * a2)),
                               fmaf(b0, b0, fmaf(b1, b1, b2 * b2)));
        rmA[p] = 3.0e38f; rmB[p] = 3.0e38f;
    }

    // mainloop: j warp-uniform (broadcast LDS.128 x2); each warp writes
    // scol[wid][j] exactly once (no RMW, no init, no races).
#pragma unroll 2
    for (int j = 0; j < SEG; j++) {
        const ulonglong2* row = (const ulonglong2*)sy[j];
        const ulonglong2 r0 = row[0];   // {-2y0 | -2y1}
        const ulonglong2 r1 = row[1];   // {-2y2 |  yw }
        F2 d0, d1, d2, d3;
        d0.u = fma2(xp0[0].u, r0.x, fma2(xp1[0].u, r0.y,
                fma2(xp2[0].u, r1.x, add2(xnp[0].u, r1.y))));
        d1.u = fma2(xp0[1].u, r0.x, fma2(xp1[1].u, r0.y,
                fma2(xp2[1].u, r1.x, add2(xnp[1].u, r1.y))));
        d2.u = fma2(xp0[2].u, r0.x, fma2(xp1[2].u, r0.y,
                fma2(xp2[2].u, r1.x, add2(xnp[2].u, r1.y))));
        d3.u = fma2(xp0[3].u, r0.x, fma2(xp1[3].u, r0.y,
                fma2(xp2[3].u, r1.x, add2(xnp[3].u, r1.y))));
        rmA[0] = fminf(rmA[0], d0.f.x);  rmB[0] = fminf(rmB[0], d0.f.y);
        rmA[1] = fminf(rmA[1], d1.f.x);  rmB[1] = fminf(rmB[1], d1.f.y);
        rmA[2] = fminf(rmA[2], d2.f.x);  rmB[2] = fminf(rmB[2], d2.f.y);
        rmA[3] = fminf(rmA[3], d3.f.x);  rmB[3] = fminf(rmB[3], d3.f.y);
        // col fold (8 -> 1), clamp >= 0 (matches reference max(d2,0); also
        // makes int-encoded REDUX ordering exact), then warp-min.
        float f = fminf(fminf(fminf(d0.f.x, d0.f.y), fminf(d1.f.x, d1.f.y)),
                        fminf(fminf(d2.f.x, d2.f.y), fminf(d3.f.x, d3.f.y)));
        f = fmaxf(f, 0.f);
        int m = __reduce_min_sync(0xffffffffu, __float_as_int(f));
        if (lane == 0) scol[wid][j] = __int_as_float(m);
    }

    // pred-side partial mins (single writer, plain store)
#pragma unroll
    for (int p = 0; p < 4; p++) {
        g_rowpart[ys * (B_ * N_) + b * N_ + pbase + p * TPB]       = fmaxf(rmA[p], 0.f);
        g_rowpart[ys * (B_ * N_) + b * N_ + pbase + (p + 4) * TPB] = fmaxf(rmB[p], 0.f);
    }

    // targ-side: merge 4 warp-private arrays, plain store
    __syncthreads();
    for (int jj = tid; jj < SEG; jj += TPB) {
        float m = scol[0][jj];
#pragma unroll
        for (int w = 1; w < NWARP; w++) m = fminf(m, scol[w][jj]);
        g_colpart[xt * (B_ * N_) + b * N_ + m0 + jj] = m;  // already clamped
    }
}

// -------- fused reduce + final (threadfence reduction; last block finalizes) --------
__global__ void reduce_final_kernel(float* __restrict__ out) {
    __shared__ float red[FTPB];
    __shared__ int   amLast;
    const int tid = threadIdx.x;
    const int gid = blockIdx.x * FTPB + tid;
    const int gsz = RED_BLOCKS * FTPB;   // 16384

    // fold partial mins (float4-vectorized), sqrt, accumulate
    float s = 0.f;
    const float4* rp4 = (const float4*)g_rowpart;
    const float4* cp4 = (const float4*)g_colpart;
    for (int i = gid; i < B_ * N_ / 4; i += gsz) {
        float4 m = rp4[i];
#pragma unroll
        for (int t = 1; t < YS; t++) {
            float4 v = rp4[t * (B_ * N_ / 4) + i];
            m.x = fminf(m.x, v.x); m.y = fminf(m.y, v.y);
            m.z = fminf(m.z, v.z); m.w = fminf(m.w, v.w);
        }
        s += sqrtf(m.x) + sqrtf(m.y) + sqrtf(m.z) + sqrtf(m.w);
    }
    for (int i = gid; i < B_ * N_ / 4; i += gsz) {
        float4 m = cp4[i];
#pragma unroll
        for (int t = 1; t < XT; t++) {
            float4 v = cp4[t * (B_ * N_ / 4) + i];
            m.x = fminf(m.x, v.x); m.y = fminf(m.y, v.y);
            m.z = fminf(m.z, v.z); m.w = fminf(m.w, v.w);
        }
        s += sqrtf(m.x) + sqrtf(m.y) + sqrtf(m.z) + sqrtf(m.w);
    }
    red[tid] = s; __syncthreads();
    for (int o = FTPB / 2; o > 0; o >>= 1) {
        if (tid < o) red[tid] += red[tid + o];
        __syncthreads();
    }
    if (tid == 0) g_part2[blockIdx.x] = red[0];

    // last-block-done detection
    __threadfence();
    if (tid == 0) {
        int prev = atomicAdd(&g_done, 1);
        amLast = (prev == RED_BLOCKS - 1);
    }
    __syncthreads();
    if (!amLast) return;

    // final weighted sum (deterministic fixed-order tree)
    float c = (tid < RED_BLOCKS) ? g_part2[tid] : 0.f;
    red[tid] = c; __syncthreads();
    for (int o = FTPB / 2; o > 0; o >>= 1) {
        if (tid < o) red[tid] += red[tid + o];
        __syncthreads();
    }
    float cham = red[0]; __syncthreads();

    float sums[3];
#pragma unroll
    for (int t = 0; t < 3; t++) {
        float v = (tid < SL_BLOCKS) ? g_part[t * SL_BLOCKS + tid] : 0.f;
        red[tid] = v; __syncthreads();
        for (int o = FTPB / 2; o > 0; o >>= 1) {
            if (tid < o) red[tid] += red[tid + o];
            __syncthreads();
        }
        sums[t] = red[0]; __syncthreads();
    }

    if (tid == 0) {
        g_done = 0;  // reset for next graph replay
        float vertex_loss  = sums[0] / (float)(B_ * N_ * 3);
        float smooth_loss  = sums[1] / (float)(B_ * (N_ - 1));
        float sym_loss     = sums[2] / (float)(B_ * (N_ / 2) * 3);
        float chamfer_loss = cham    / (float)(B_ * N_);
        out[0] = 1.0f * vertex_loss + 0.1f * smooth_loss
               + 0.05f * sym_loss + 0.1f * chamfer_loss;
    }
}

extern "C" void kernel_launch(void* const* d_in, const int* in_sizes, int n_in,
                              void* d_out, int out_size) {
    const float* pred = (const float*)d_in[0];
    const float* targ = (const float*)d_in[1];
    float* out = (float*)d_out;
    (void)in_sizes; (void)n_in; (void)out_size;

    mega_kernel<<<SL_BLOCKS + CHAM_BLOCKS, TPB>>>(pred, targ);  // 1184 = 8*148
    reduce_final_kernel<<<RED_BLOCKS, FTPB>>>(out);
}